// round 8
// baseline (speedup 1.0000x reference)
#include <cuda_runtime.h>
#include <math.h>

// RT-DETR post-processing, two kernels:
//   K1 : per-query max/argmax over logits (no sigmoid!) -> raw u64 keys
//   K2 : 2-CTA cluster per batch: convert keys to score space (bit-identical
//        to the old k1 math), sort each 512-half DESC, DSMEM halver keeps the
//        top 512, short bitonic merge, emit top-300.
// Output (concat f32): scores[256,300] | labels[256,300] | boxes[256,300,4]

#define NB      256
#define NQ      1000
#define NC      80
#define SORT_N  1024
#define TOPK    300
#define THRESH  0.05f

typedef unsigned long long u64;
typedef unsigned int       u32;

__device__ u64 g_keys[NB * SORT_N];   // 2 MB scratch (k1 -> k2)

__device__ __forceinline__ u32 f2ord(u32 b) {            // order-preserving f32->u32
    return (b & 0x80000000u) ? ~b : (b | 0x80000000u);
}
__device__ __forceinline__ u32 ord2f(u32 u) {
    return (u & 0x80000000u) ? (u ^ 0x80000000u) : ~u;
}

// ---------------------------------------------------------------------------
// K1: grid=8000, block=256 (8 warps); each warp handles 4 consecutive queries.
// Minimal tail: store [ord(logit) 32 | (0xFFFF-q) 16 | label 16], no sigmoid.
// ---------------------------------------------------------------------------
__global__ __launch_bounds__(256)
void k1_argmax(const float* __restrict__ logits)
{
    const int warp = threadIdx.x >> 5;
    const int lane = threadIdx.x & 31;
    const int f0   = (blockIdx.x * 8 + warp) * 4;     // first flat query (b*NQ+q)

    const float4* base = (const float4*)logits + (size_t)f0 * (NC / 4);

    u32 u[4]; int id[4];
    #pragma unroll
    for (int j = 0; j < 4; j++) { u[j] = 0u; id[j] = 1023; }

    if (lane < NC / 4) {                              // 20 lanes carry data
        #pragma unroll
        for (int j = 0; j < 4; j++) {                 // 4 independent LDG.128
            float4 x = base[j * (NC / 4) + lane];
            float v = x.x; int idx = lane * 4;
            if (x.y > v) { v = x.y; idx = lane * 4 + 1; }
            if (x.z > v) { v = x.z; idx = lane * 4 + 2; }
            if (x.w > v) { v = x.w; idx = lane * 4 + 3; }
            u[j]  = f2ord(__float_as_uint(v));
            id[j] = idx;
        }
    }

    u32 m[4], am[4];
    #pragma unroll
    for (int j = 0; j < 4; j++) {
        m[j] = __reduce_max_sync(0xffffffffu, u[j]);
        u32 cand = (u[j] == m[j]) ? (u32)id[j] : 1023u;   // ties -> lowest class
        am[j] = __reduce_min_sync(0xffffffffu, cand);
    }

    if (lane < 4) {   // lanes 0..3 finalize one query each (coalesced 32B store)
        u32 mm = (lane == 0) ? m[0]  : (lane == 1) ? m[1]  : (lane == 2) ? m[2]  : m[3];
        u32 aa = (lane == 0) ? am[0] : (lane == 1) ? am[1] : (lane == 2) ? am[2] : am[3];
        int f = f0 + lane;
        int b = f / NQ;
        int q = f - b * NQ;
        g_keys[b * SORT_N + q] = ((u64)mm << 32)
                               | ((u64)(u32)(0xFFFF - q) << 16)
                               | (u64)aa;
    }
}

// ---------------------------------------------------------------------------
// Cluster / DSMEM helpers
// ---------------------------------------------------------------------------
__device__ __forceinline__ u32 smem_u32(const void* p) {
    u32 a;
    asm("{ .reg .u64 t; cvta.to.shared.u64 t, %1; cvt.u32.u64 %0, t; }"
        : "=r"(a) : "l"(p));
    return a;
}
__device__ __forceinline__ u32 mapa_rank(u32 addr, u32 rank) {
    u32 o;
    asm("mapa.shared::cluster.u32 %0, %1, %2;" : "=r"(o) : "r"(addr), "r"(rank));
    return o;
}
__device__ __forceinline__ u64 dsmem_ld64(u32 addr) {
    u64 v;
    asm volatile("ld.shared::cluster.b64 %0, [%1];" : "=l"(v) : "r"(addr));
    return v;
}
#define CLUSTER_ARRIVE() asm volatile("barrier.cluster.arrive.aligned;" ::: "memory")
#define CLUSTER_WAIT()   asm volatile("barrier.cluster.wait.aligned;"   ::: "memory")

// ---------------------------------------------------------------------------
// Bitonic helpers (descending only; hybrid register/shfl + smem)
// ---------------------------------------------------------------------------
__device__ __forceinline__ u64 keep_mm(u64 v, u64 pv, bool kmax) {
    return kmax ? (v > pv ? v : pv) : (v < pv ? v : pv);
}

template<int K, int JSTART>
__device__ __forceinline__ void reg_merge(u64 &v0, u64 &v1, int e0, int e1)
{
    #pragma unroll
    for (int j = JSTART; j >= 1; j >>= 1) {
        if (j == 32) {
            bool desc = ((e0 & K) == 0);
            if (desc ? (v0 < v1) : (v0 > v1)) { u64 t = v0; v0 = v1; v1 = t; }
        } else {
            u64 p0 = __shfl_xor_sync(0xffffffffu, v0, j);
            u64 p1 = __shfl_xor_sync(0xffffffffu, v1, j);
            bool desc0 = ((e0 & K) == 0);
            bool desc1 = ((e1 & K) == 0);
            bool low   = ((e0 & j) == 0);
            v0 = keep_mm(v0, p0, desc0 == low);
            v1 = keep_mm(v1, p1, desc1 == low);
        }
    }
}

__device__ __forceinline__ void smem_step(u64* keys, int t, int j, int k)
{
    int i  = ((t & ~(j - 1)) << 1) | (t & (j - 1));
    int ix = i + j;
    u64 a = keys[i];
    u64 c = keys[ix];
    bool desc = ((i & k) == 0);
    if (desc ? (a < c) : (a > c)) { keys[i] = c; keys[ix] = a; }
}

// Convert raw [ord(logit)|q|label] key to score-space key. Bit-identical to
// the sigmoid/threshold/f2ord sequence the old k1 applied.
__device__ __forceinline__ u64 convert_key(u64 raw)
{
    u32 mo = (u32)(raw >> 32);
    float v     = __uint_as_float(ord2f(mo));
    float score = 1.0f / (1.0f + expf(-v));
    float ms    = (score > THRESH) ? score : -1.0f;
    u32 sb = f2ord(__float_as_uint(ms));
    return ((u64)sb << 32) | (raw & 0xFFFFFFFFull);
}

// ---------------------------------------------------------------------------
// Emit one ranked entry
// ---------------------------------------------------------------------------
__device__ __forceinline__ void emit_one(u64 key, int e, int b,
                                         float img_w, float img_h,
                                         const float* __restrict__ boxes,
                                         float* __restrict__ out)
{
    const int S = NB * TOPK;
    u32 u    = (u32)(key >> 32);
    float ms = __uint_as_float(ord2f(u));
    int q    = 0xFFFF - (int)((key >> 16) & 0xFFFFu);
    int lab  = (int)(key & 0xFFFFu);
    bool valid = ms > THRESH;

    int o = b * TOPK + e;
    out[o]     = valid ? ms : 0.0f;
    out[S + o] = valid ? (float)lab : -1.0f;

    float4 bx = ((const float4*)boxes)[(size_t)b * NQ + q];
    float x0 = (bx.x - 0.5f * bx.z) * img_w;
    float y0 = (bx.y - 0.5f * bx.w) * img_h;
    float x1 = (bx.x + 0.5f * bx.z) * img_w;
    float y1 = (bx.y + 0.5f * bx.w) * img_h;
    ((float4*)(out + 2 * S))[o] = valid ? make_float4(x0, y0, x1, y1)
                                        : make_float4(0.f, 0.f, 0.f, 0.f);
}

// ---------------------------------------------------------------------------
// K2: grid=512 (cluster pairs), block=256. Each CTA sorts its 512-half DESC
// in smem; rank 0 then halves via DSMEM, merges 512, emits top-300.
// ---------------------------------------------------------------------------
__global__ __launch_bounds__(256) __cluster_dims__(2, 1, 1)
void k2_sort_merge_emit(const float* __restrict__ boxes,
                        const float* __restrict__ tsizes,
                        float* __restrict__ out)
{
    __shared__ u64 keys[512];

    const int b    = blockIdx.x >> 1;
    const int h    = blockIdx.x & 1;      // == cluster rank for (2,1,1)
    const int t    = threadIdx.x;
    const int w    = t >> 5;
    const int l    = t & 31;
    const int e0   = 64 * w + l;
    const int e1   = e0 + 32;

    const u64* gk = g_keys + (size_t)b * SORT_N + h * 512;

    // Load + convert to score-space keys (padding sorts below all real keys)
    int f0g = h * 512 + e0, f1g = h * 512 + e1;
    u64 v0 = (f0g < NQ) ? convert_key(gk[e0]) : 0ull;
    u64 v1 = (f1g < NQ) ? convert_key(gk[e1]) : 0ull;

    // ---- sort 512 descending (hybrid register/shfl + smem) ----
    reg_merge<2,  1 >(v0, v1, e0, e1);
    reg_merge<4,  2 >(v0, v1, e0, e1);
    reg_merge<8,  4 >(v0, v1, e0, e1);
    reg_merge<16, 8 >(v0, v1, e0, e1);
    reg_merge<32, 16>(v0, v1, e0, e1);
    reg_merge<64, 32>(v0, v1, e0, e1);
    keys[e0] = v0; keys[e1] = v1;
    __syncthreads();

    smem_step(keys, t, 64, 128);  __syncthreads();
    v0 = keys[e0]; v1 = keys[e1];
    reg_merge<128, 32>(v0, v1, e0, e1);
    keys[e0] = v0; keys[e1] = v1;
    __syncthreads();

    smem_step(keys, t, 128, 256); __syncthreads();
    smem_step(keys, t,  64, 256); __syncthreads();
    v0 = keys[e0]; v1 = keys[e1];
    reg_merge<256, 32>(v0, v1, e0, e1);
    keys[e0] = v0; keys[e1] = v1;
    __syncthreads();

    smem_step(keys, t, 256, 512); __syncthreads();
    smem_step(keys, t, 128, 512); __syncthreads();
    smem_step(keys, t,  64, 512); __syncthreads();
    v0 = keys[e0]; v1 = keys[e1];
    reg_merge<512, 32>(v0, v1, e0, e1);
    keys[e0] = v0; keys[e1] = v1;

    // ---- cluster barrier #1: both halves sorted & visible ----
    CLUSTER_ARRIVE();
    CLUSTER_WAIT();

    if (h == 0) {
        // Halver over the two DESC halves: C[i] = max(A[i], B[511-i]) holds
        // the 512 largest and is bitonic. Peer half read via DSMEM.
        u32 my_base   = smem_u32(keys);
        u32 peer_base = mapa_rank(my_base, 1);

        u64 a0 = keys[t];       u64 b0 = dsmem_ld64(peer_base + (u32)(511 - t) * 8);
        u64 a1 = keys[t + 256]; u64 b1 = dsmem_ld64(peer_base + (u32)(255 - t) * 8);

        // Done reading peer smem -> release rank 1.
        CLUSTER_ARRIVE();
        CLUSTER_WAIT();

        keys[t]       = (a0 > b0) ? a0 : b0;
        keys[t + 256] = (a1 > b1) ? a1 : b1;
        __syncthreads();

        // Bitonic merge of 512, descending
        smem_step(keys, t, 256, 512); __syncthreads();
        smem_step(keys, t, 128, 512); __syncthreads();
        smem_step(keys, t,  64, 512); __syncthreads();

        u64 m0 = keys[e0], m1 = keys[e1];
        reg_merge<1024, 32>(m0, m1, e0, e1);   // K>511 => all desc

        const float img_h = tsizes[2 * b + 0];
        const float img_w = tsizes[2 * b + 1];
        if (e0 < TOPK) emit_one(m0, e0, b, img_w, img_h, boxes, out);
        if (e1 < TOPK) emit_one(m1, e1, b, img_w, img_h, boxes, out);
    } else {
        // Stay alive until rank 0 has finished reading our smem.
        CLUSTER_ARRIVE();
        CLUSTER_WAIT();
    }
}

// ---------------------------------------------------------------------------
extern "C" void kernel_launch(void* const* d_in, const int* in_sizes, int n_in,
                              void* d_out, int out_size)
{
    const float* logits = (const float*)d_in[0];   // (256,1000,80) f32
    const float* boxes  = (const float*)d_in[1];   // (256,1000,4)  f32
    const float* tsizes = (const float*)d_in[2];   // (256,2)       f32
    float* out = (float*)d_out;                    // 460800 f32

    k1_argmax<<<8000, 256>>>(logits);
    k2_sort_merge_emit<<<512, 256>>>(boxes, tsizes, out);
}

// round 9
// speedup vs baseline: 1.0033x; 1.0033x over previous
#include <cuda_runtime.h>
#include <math.h>

// RT-DETR post-processing, three kernels:
//   K1 : per-query max/argmax over logits (no sigmoid) -> raw u64 keys
//   K2a: per (batch, half): convert to score space (bit-identical math),
//        bitonic-sort 512 keys DESC, write back
//   K2b: bitonic halver (keep top 512) + short merge + emit top-300
// Output (concat f32): scores[256,300] | labels[256,300] | boxes[256,300,4]

#define NB      256
#define NQ      1000
#define NC      80
#define SORT_N  1024
#define TOPK    300
#define THRESH  0.05f

typedef unsigned long long u64;
typedef unsigned int       u32;

__device__ u64 g_keys[NB * SORT_N];   // 2 MB scratch

__device__ __forceinline__ u32 f2ord(u32 b) {            // order-preserving f32->u32
    return (b & 0x80000000u) ? ~b : (b | 0x80000000u);
}
__device__ __forceinline__ u32 ord2f(u32 u) {
    return (u & 0x80000000u) ? (u ^ 0x80000000u) : ~u;
}

// ---------------------------------------------------------------------------
// K1: grid=8000, block=256 (8 warps); each warp handles 4 consecutive queries.
// Minimal tail: store [ord(logit) 32 | (0xFFFF-q) 16 | label 16], no sigmoid.
// ---------------------------------------------------------------------------
__global__ __launch_bounds__(256)
void k1_argmax(const float* __restrict__ logits)
{
    const int warp = threadIdx.x >> 5;
    const int lane = threadIdx.x & 31;
    const int f0   = (blockIdx.x * 8 + warp) * 4;     // first flat query (b*NQ+q)

    const float4* base = (const float4*)logits + (size_t)f0 * (NC / 4);

    u32 u[4]; int id[4];
    #pragma unroll
    for (int j = 0; j < 4; j++) { u[j] = 0u; id[j] = 1023; }

    if (lane < NC / 4) {                              // 20 lanes carry data
        #pragma unroll
        for (int j = 0; j < 4; j++) {                 // 4 independent LDG.128
            float4 x = base[j * (NC / 4) + lane];
            float v = x.x; int idx = lane * 4;
            if (x.y > v) { v = x.y; idx = lane * 4 + 1; }
            if (x.z > v) { v = x.z; idx = lane * 4 + 2; }
            if (x.w > v) { v = x.w; idx = lane * 4 + 3; }
            u[j]  = f2ord(__float_as_uint(v));
            id[j] = idx;
        }
    }

    u32 m[4], am[4];
    #pragma unroll
    for (int j = 0; j < 4; j++) {
        m[j] = __reduce_max_sync(0xffffffffu, u[j]);
        u32 cand = (u[j] == m[j]) ? (u32)id[j] : 1023u;   // ties -> lowest class
        am[j] = __reduce_min_sync(0xffffffffu, cand);
    }

    if (lane < 4) {   // lanes 0..3 finalize one query each (coalesced 32B store)
        u32 mm = (lane == 0) ? m[0]  : (lane == 1) ? m[1]  : (lane == 2) ? m[2]  : m[3];
        u32 aa = (lane == 0) ? am[0] : (lane == 1) ? am[1] : (lane == 2) ? am[2] : am[3];
        int f = f0 + lane;
        int b = f / NQ;
        int q = f - b * NQ;
        g_keys[b * SORT_N + q] = ((u64)mm << 32)
                               | ((u64)(u32)(0xFFFF - q) << 16)
                               | (u64)aa;
    }
}

// ---------------------------------------------------------------------------
// Bitonic helpers (descending only; hybrid register/shfl + smem)
// ---------------------------------------------------------------------------
__device__ __forceinline__ u64 keep_mm(u64 v, u64 pv, bool kmax) {
    return kmax ? (v > pv ? v : pv) : (v < pv ? v : pv);
}

template<int K, int JSTART>
__device__ __forceinline__ void reg_merge(u64 &v0, u64 &v1, int e0, int e1)
{
    #pragma unroll
    for (int j = JSTART; j >= 1; j >>= 1) {
        if (j == 32) {
            bool desc = ((e0 & K) == 0);
            if (desc ? (v0 < v1) : (v0 > v1)) { u64 t = v0; v0 = v1; v1 = t; }
        } else {
            u64 p0 = __shfl_xor_sync(0xffffffffu, v0, j);
            u64 p1 = __shfl_xor_sync(0xffffffffu, v1, j);
            bool desc0 = ((e0 & K) == 0);
            bool desc1 = ((e1 & K) == 0);
            bool low   = ((e0 & j) == 0);
            v0 = keep_mm(v0, p0, desc0 == low);
            v1 = keep_mm(v1, p1, desc1 == low);
        }
    }
}

__device__ __forceinline__ void smem_step(u64* keys, int t, int j, int k)
{
    int i  = ((t & ~(j - 1)) << 1) | (t & (j - 1));
    int ix = i + j;
    u64 a = keys[i];
    u64 c = keys[ix];
    bool desc = ((i & k) == 0);
    if (desc ? (a < c) : (a > c)) { keys[i] = c; keys[ix] = a; }
}

// Convert raw [ord(logit)|q|label] key to score-space key. Bit-identical to
// applying sigmoid/threshold/f2ord before packing.
__device__ __forceinline__ u64 convert_key(u64 raw)
{
    u32 mo = (u32)(raw >> 32);
    float v     = __uint_as_float(ord2f(mo));
    float score = 1.0f / (1.0f + expf(-v));
    float ms    = (score > THRESH) ? score : -1.0f;
    u32 sb = f2ord(__float_as_uint(ms));
    return ((u64)sb << 32) | (raw & 0xFFFFFFFFull);
}

// ---------------------------------------------------------------------------
// K2a: grid=(2, 256), block=256. Convert + sort its 512 keys DESC.
// Thread t (warp w 0..7, lane l) owns local elements e0=64w+l, e1=e0+32.
// ---------------------------------------------------------------------------
__global__ __launch_bounds__(256)
void k2a_sort512()
{
    __shared__ u64 keys[512];

    const int h  = blockIdx.x;
    const int b  = blockIdx.y;
    const int t  = threadIdx.x;
    const int w  = t >> 5;
    const int l  = t & 31;
    const int e0 = 64 * w + l;
    const int e1 = e0 + 32;

    u64* gk = g_keys + (size_t)b * SORT_N + h * 512;

    int f0 = h * 512 + e0, f1 = h * 512 + e1;
    u64 v0 = (f0 < NQ) ? convert_key(gk[e0]) : 0ull;   // padding below all real
    u64 v1 = (f1 < NQ) ? convert_key(gk[e1]) : 0ull;

    reg_merge<2,  1 >(v0, v1, e0, e1);
    reg_merge<4,  2 >(v0, v1, e0, e1);
    reg_merge<8,  4 >(v0, v1, e0, e1);
    reg_merge<16, 8 >(v0, v1, e0, e1);
    reg_merge<32, 16>(v0, v1, e0, e1);
    reg_merge<64, 32>(v0, v1, e0, e1);
    keys[e0] = v0; keys[e1] = v1;
    __syncthreads();

    smem_step(keys, t, 64, 128);  __syncthreads();
    v0 = keys[e0]; v1 = keys[e1];
    reg_merge<128, 32>(v0, v1, e0, e1);
    keys[e0] = v0; keys[e1] = v1;
    __syncthreads();

    smem_step(keys, t, 128, 256); __syncthreads();
    smem_step(keys, t,  64, 256); __syncthreads();
    v0 = keys[e0]; v1 = keys[e1];
    reg_merge<256, 32>(v0, v1, e0, e1);
    keys[e0] = v0; keys[e1] = v1;
    __syncthreads();

    smem_step(keys, t, 256, 512); __syncthreads();
    smem_step(keys, t, 128, 512); __syncthreads();
    smem_step(keys, t,  64, 512); __syncthreads();
    v0 = keys[e0]; v1 = keys[e1];
    reg_merge<512, 32>(v0, v1, e0, e1);

    gk[e0] = v0; gk[e1] = v1;             // fully sorted descending
}

// ---------------------------------------------------------------------------
// K2b: grid=256, block=256. Halver keeps top 512 (bitonic), merge, emit 300.
// ---------------------------------------------------------------------------
__device__ __forceinline__ void emit_one(u64 key, int e, int b,
                                         float img_w, float img_h,
                                         const float* __restrict__ boxes,
                                         float* __restrict__ out)
{
    const int S = NB * TOPK;
    u32 u    = (u32)(key >> 32);
    float ms = __uint_as_float(ord2f(u));
    int q    = 0xFFFF - (int)((key >> 16) & 0xFFFFu);
    int lab  = (int)(key & 0xFFFFu);
    bool valid = ms > THRESH;

    int o = b * TOPK + e;
    out[o]     = valid ? ms : 0.0f;
    out[S + o] = valid ? (float)lab : -1.0f;

    float4 bx = ((const float4*)boxes)[(size_t)b * NQ + q];
    float x0 = (bx.x - 0.5f * bx.z) * img_w;
    float y0 = (bx.y - 0.5f * bx.w) * img_h;
    float x1 = (bx.x + 0.5f * bx.z) * img_w;
    float y1 = (bx.y + 0.5f * bx.w) * img_h;
    ((float4*)(out + 2 * S))[o] = valid ? make_float4(x0, y0, x1, y1)
                                        : make_float4(0.f, 0.f, 0.f, 0.f);
}

__global__ __launch_bounds__(256)
void k2b_merge_emit(const float* __restrict__ boxes,
                    const float* __restrict__ tsizes,
                    float* __restrict__ out)
{
    __shared__ u64 keys[512];

    const int b = blockIdx.x;
    const int t = threadIdx.x;
    const int w = t >> 5;
    const int l = t & 31;
    const int e0 = 64 * w + l;     // 0..511
    const int e1 = e0 + 32;

    const u64* gk = g_keys + (size_t)b * SORT_N;

    // Halver: both halves sorted DESC; C[i] = max(A[i], B[511-i]) holds the
    // 512 largest keys and is bitonic. Bottom half never touched again.
    {
        u64 a0 = gk[t];         u64 b0 = gk[1023 - t];
        u64 a1 = gk[t + 256];   u64 b1 = gk[767  - t];
        keys[t]       = (a0 > b0) ? a0 : b0;
        keys[t + 256] = (a1 > b1) ? a1 : b1;
    }
    __syncthreads();

    // Bitonic merge of 512, descending (k=512 => all desc)
    smem_step(keys, t, 256, 512); __syncthreads();
    smem_step(keys, t, 128, 512); __syncthreads();
    smem_step(keys, t,  64, 512); __syncthreads();

    u64 v0 = keys[e0], v1 = keys[e1];
    reg_merge<1024, 32>(v0, v1, e0, e1);   // K>511 => all desc

    const float img_h = tsizes[2 * b + 0];
    const float img_w = tsizes[2 * b + 1];
    if (e0 < TOPK) emit_one(v0, e0, b, img_w, img_h, boxes, out);
    if (e1 < TOPK) emit_one(v1, e1, b, img_w, img_h, boxes, out);
}

// ---------------------------------------------------------------------------
extern "C" void kernel_launch(void* const* d_in, const int* in_sizes, int n_in,
                              void* d_out, int out_size)
{
    const float* logits = (const float*)d_in[0];   // (256,1000,80) f32
    const float* boxes  = (const float*)d_in[1];   // (256,1000,4)  f32
    const float* tsizes = (const float*)d_in[2];   // (256,2)       f32
    float* out = (float*)d_out;                    // 460800 f32

    k1_argmax<<<8000, 256>>>(logits);
    k2a_sort512<<<dim3(2, NB), 256>>>();
    k2b_merge_emit<<<NB, 256>>>(boxes, tsizes, out);
}